// round 15
// baseline (speedup 1.0000x reference)
#include <cuda_runtime.h>
#include <math.h>

#define BB 16
#define NN 8
#define TT 65536
#define CHUNKS 32
#define TPB 256
#define TPC (TT / CHUNKS)          // 2048 floats per chunk per row
#define SCOL4 128                  // float4 columns per substep (512 floats)
#define SUB ((TPC / 4) / SCOL4)    // 4 substeps per chunk
#define NSTAGE 3
#define NCPB 80                    // cells per batch: 64 cross + 8 nx + 8 ny
#define NCELL 64

// Scratch: [BB][80 cells][CHUNKS] -> cross-chunk sum contiguous (float4-able).
__device__ float g_part[BB * NCPB * CHUNKS];
__device__ unsigned int g_ctr;     // zero-init; last block resets to 0

__device__ __forceinline__ void cp16(void* sdst, const void* gsrc) {
    unsigned int sa = (unsigned int)__cvta_generic_to_shared(sdst);
    asm volatile("cp.async.cg.shared.global [%0], [%1], 16;" :: "r"(sa), "l"(gsrc) : "memory");
}
__device__ __forceinline__ void cp_commit() {
    asm volatile("cp.async.commit_group;" ::: "memory");
}
template <int N> __device__ __forceinline__ void cp_wait() {
    asm volatile("cp.async.wait_group %0;" :: "n"(N) : "memory");
}

__global__ __launch_bounds__(TPB, 4)
void sp_fused(const float* __restrict__ inp, const float* __restrict__ tgt,
              float* __restrict__ out, int out_size) {
    const int b = blockIdx.y;
    const int chunk = blockIdx.x;
    const int tid = threadIdx.x;
    const int col = tid & 127;      // float4 column within substep
    const int h = tid >> 7;         // 0..1: X rows 4h..4h+3; ny rows 4h..4h+3
    const int warp = tid >> 5;
    const int lane = tid & 31;

    const float4* __restrict__ X = reinterpret_cast<const float4*>(inp)
                                   + (size_t)b * NN * (TT / 4) + (size_t)chunk * (TPC / 4);
    const float4* __restrict__ Y = reinterpret_cast<const float4*>(tgt)
                                   + (size_t)b * NN * (TT / 4) + (size_t)chunk * (TPC / 4);

    __shared__ float4 ybuf[NSTAGE][NN][SCOL4];   // 48 KB, 3-stage Y ring
    __shared__ float sred[TPB / 32][40];         // 32 cross + 4 nx + 4 ny per warp

    // ---- Prologue: cp.async Y stages 0,1 (4 rows per thread each) ----
#pragma unroll
    for (int s = 0; s < 2; s++) {
#pragma unroll
        for (int q = 0; q < 4; q++) {
            const int row = 2 * q + h;
            cp16(&ybuf[s][row][col], &Y[(size_t)row * (TT / 4) + s * SCOL4 + col]);
        }
        cp_commit();
    }

    float acc[4][NN];
#pragma unroll
    for (int i = 0; i < 4; i++)
#pragma unroll
        for (int j = 0; j < NN; j++) acc[i][j] = 0.f;
    float nx[4] = {0.f, 0.f, 0.f, 0.f};
    float nyl[4] = {0.f, 0.f, 0.f, 0.f};

    // ---- Main pipeline: wait stage s -> barrier -> issue s+2 -> load X -> compute ----
#pragma unroll
    for (int s = 0; s < SUB; s++) {
        if (s == SUB - 1) cp_wait<0>(); else cp_wait<1>();
        __syncthreads();   // stage s visible; ring slot (s+2)%3 fully consumed

        if (s + 2 < SUB) {
            const int buf = (s + 2) % NSTAGE;
#pragma unroll
            for (int q = 0; q < 4; q++) {
                const int row = 2 * q + h;
                cp16(&ybuf[buf][row][col],
                     &Y[(size_t)row * (TT / 4) + (s + 2) * SCOL4 + col]);
            }
            cp_commit();
        }

        float4 x[4];
#pragma unroll
        for (int i = 0; i < 4; i++)
            x[i] = __ldg(&X[(size_t)(4 * h + i) * (TT / 4) + s * SCOL4 + col]);

#pragma unroll
        for (int i = 0; i < 4; i++) {
            nx[i] = fmaf(x[i].x, x[i].x, nx[i]);
            nx[i] = fmaf(x[i].y, x[i].y, nx[i]);
            nx[i] = fmaf(x[i].z, x[i].z, nx[i]);
            nx[i] = fmaf(x[i].w, x[i].w, nx[i]);
        }
        const float4 (*yb)[SCOL4] = ybuf[s % NSTAGE];
#pragma unroll
        for (int j = 0; j < NN; j++) {
            const float4 y = yb[j][col];
#pragma unroll
            for (int i = 0; i < 4; i++) {
                acc[i][j] = fmaf(x[i].x, y.x, acc[i][j]);
                acc[i][j] = fmaf(x[i].y, y.y, acc[i][j]);
                acc[i][j] = fmaf(x[i].z, y.z, acc[i][j]);
                acc[i][j] = fmaf(x[i].w, y.w, acc[i][j]);
            }
            if ((j >> 2) == h) {   // uniform per warp: no divergence
                const int jj = j & 3;
                nyl[jj] = fmaf(y.x, y.x, nyl[jj]);
                nyl[jj] = fmaf(y.y, y.y, nyl[jj]);
                nyl[jj] = fmaf(y.z, y.z, nyl[jj]);
                nyl[jj] = fmaf(y.w, y.w, nyl[jj]);
            }
        }
    }

    // ---- Warp tree-reduce 40 values, stage per-warp, combine across warps ----
#pragma unroll
    for (int i = 0; i < 4; i++)
#pragma unroll
        for (int j = 0; j < NN; j++) {
            float v = acc[i][j];
            v += __shfl_xor_sync(0xffffffffu, v, 16);
            v += __shfl_xor_sync(0xffffffffu, v, 8);
            v += __shfl_xor_sync(0xffffffffu, v, 4);
            v += __shfl_xor_sync(0xffffffffu, v, 2);
            v += __shfl_xor_sync(0xffffffffu, v, 1);
            acc[i][j] = v;
        }
#pragma unroll
    for (int q = 0; q < 4; q++) {
        float v = nx[q];
        v += __shfl_xor_sync(0xffffffffu, v, 16);
        v += __shfl_xor_sync(0xffffffffu, v, 8);
        v += __shfl_xor_sync(0xffffffffu, v, 4);
        v += __shfl_xor_sync(0xffffffffu, v, 2);
        v += __shfl_xor_sync(0xffffffffu, v, 1);
        nx[q] = v;
        float w = nyl[q];
        w += __shfl_xor_sync(0xffffffffu, w, 16);
        w += __shfl_xor_sync(0xffffffffu, w, 8);
        w += __shfl_xor_sync(0xffffffffu, w, 4);
        w += __shfl_xor_sync(0xffffffffu, w, 2);
        w += __shfl_xor_sync(0xffffffffu, w, 1);
        nyl[q] = w;
    }
    if (lane == 0) {
#pragma unroll
        for (int i = 0; i < 4; i++)
#pragma unroll
            for (int j = 0; j < NN; j++) sred[warp][i * NN + j] = acc[i][j];
#pragma unroll
        for (int q = 0; q < 4; q++) {
            sred[warp][32 + q] = nx[q];
            sred[warp][36 + q] = nyl[q];
        }
    }
    __syncthreads();

    // Warps 0-3 hold h=0 (i/j rows 0-3), warps 4-7 hold h=1 (rows 4-7).
    float* const gp = &g_part[(size_t)b * NCPB * CHUNKS + chunk];
    if (tid < NCELL) {                       // cross cell (i,j)
        const int ci = tid >> 3, cj = tid & 7;
        const int cg = ci >> 2, cii = ci & 3;
        float s = 0.f;
#pragma unroll
        for (int w = 0; w < 4; w++) s += sred[4 * cg + w][cii * NN + cj];
        gp[(size_t)tid * CHUNKS] = s;
    } else if (tid < NCELL + 8) {            // nx row i
        const int i = tid - NCELL;
        const int cg = i >> 2, ii = i & 3;
        float s = 0.f;
#pragma unroll
        for (int w = 0; w < 4; w++) s += sred[4 * cg + w][32 + ii];
        gp[(size_t)tid * CHUNKS] = s;
    } else if (tid < NCELL + 16) {           // ny row j
        const int j = tid - NCELL - 8;
        const int cg = j >> 2, jj = j & 3;
        float s = 0.f;
#pragma unroll
        for (int w = 0; w < 4; w++) s += sred[4 * cg + w][36 + jj];
        gp[(size_t)tid * CHUNKS] = s;
    }

    // ---- Arrival counter: last of 512 blocks finishes the job ----
    __threadfence();
    __syncthreads();
    __shared__ unsigned int s_last;
    if (tid == 0)
        s_last = (atomicAdd(&g_ctr, 1u) == (unsigned)(CHUNKS * BB - 1)) ? 1u : 0u;
    __syncthreads();
    if (!s_last) return;
    if (tid == 0) g_ctr = 0;       // reset for next graph replay

    // ---- Phase 2 (last block): chunk reduction, 32 contiguous floats/cell ----
    float* s_pl = reinterpret_cast<float*>(ybuf);   // reuse stage smem (5 KB)
    for (int cell = tid; cell < BB * NCPB; cell += TPB) {
        const float4* p = reinterpret_cast<const float4*>(&g_part[(size_t)cell * CHUNKS]);
        float s = 0.f;
#pragma unroll
        for (int q = 0; q < CHUNKS / 4; q++) {
            const float4 v = __ldcv(p + q);
            s += v.x + v.y + v.z + v.w;
        }
        s_pl[cell] = s;
    }
    __syncthreads();

    // ---- Phase 3: Sinkhorn (threads 0..127; thread = (batch sb, column sj)) ----
    float loss_t = 0.f;
    int aj[NN];
    const int sb = tid >> 3;
    const int sj = tid & 7;

    if (tid < 128) {
        const float* base = &s_pl[sb * NCPB];
        const float nyj = base[NCELL + 8 + sj];
        float pl[NN], z[NN];
#pragma unroll
        for (int i = 0; i < NN; i++) {
            // (x-y)^2 sum = nx_i + ny_j - 2*cross_ij, then mean over T
            pl[i] = (base[NCELL + i] + nyj - 2.f * base[i * NN + sj]) * (1.0f / (float)TT);
            z[i] = -pl[i];         // COLDNESS = 1
        }

#pragma unroll 1
        for (int it = 0; it < 10; it++) {
            float s = 0.f;
#pragma unroll
            for (int i = 0; i < NN; i++) s += __expf(z[i]);
            const float l = __logf(s);
#pragma unroll
            for (int i = 0; i < NN; i++) z[i] -= l;
            float e[NN];
#pragma unroll
            for (int i = 0; i < NN; i++) e[i] = __expf(z[i]);
#pragma unroll
            for (int off = 1; off < NN; off <<= 1)
#pragma unroll
                for (int i = 0; i < NN; i++)
                    e[i] += __shfl_xor_sync(0xffffffffu, e[i], off);
#pragma unroll
            for (int i = 0; i < NN; i++) z[i] -= __logf(e[i]);
        }

#pragma unroll
        for (int i = 0; i < NN; i++)
            loss_t += (pl[i] + z[i]) * __expf(z[i]);

        float av[NN];
#pragma unroll
        for (int i = 0; i < NN; i++) { av[i] = z[i]; aj[i] = sj; }
#pragma unroll
        for (int off = 1; off < NN; off <<= 1)
#pragma unroll
            for (int i = 0; i < NN; i++) {
                const float ov = __shfl_xor_sync(0xffffffffu, av[i], off);
                const int oj = __shfl_xor_sync(0xffffffffu, aj[i], off);
                if (ov > av[i] || (ov == av[i] && oj < aj[i])) { av[i] = ov; aj[i] = oj; }
            }
    }

    __shared__ float s_wloss[TPB / 32];
#pragma unroll
    for (int off = 16; off; off >>= 1)
        loss_t += __shfl_xor_sync(0xffffffffu, loss_t, off);
    if (lane == 0) s_wloss[warp] = loss_t;
    __syncthreads();
    float loss = 0.f;
    if (tid == 0) {
#pragma unroll
        for (int w = 0; w < 4; w++) loss += s_wloss[w];
        loss *= (1.0f / (float)BB);
    }

    // ---- Output: loss then pattern (fp32); defensive layouts ----
    const int full = 1 + BB * NN;   // 129
    if (out_size >= full) {
        if (tid == 0) out[0] = loss;
        if (tid < 128 && sj == 0) {
#pragma unroll
            for (int i = 0; i < NN; i++) out[1 + sb * NN + i] = (float)aj[i];
        }
        for (int idx = full + tid; idx < out_size; idx += TPB) out[idx] = 0.f;
    } else if (out_size == BB * NN) {
        if (tid < 128 && sj == 0) {
#pragma unroll
            for (int i = 0; i < NN; i++) out[sb * NN + i] = (float)aj[i];
        }
    } else {
        if (tid == 0 && out_size > 0) out[0] = loss;
        for (int idx = 1 + tid; idx < out_size; idx += TPB) out[idx] = 0.f;
    }
}

extern "C" void kernel_launch(void* const* d_in, const int* in_sizes, int n_in,
                              void* d_out, int out_size) {
    const float* inp = (const float*)d_in[0];
    const float* tgt = (const float*)d_in[1];

    dim3 grid(CHUNKS, BB);
    sp_fused<<<grid, TPB>>>(inp, tgt, (float*)d_out, out_size);
}

// round 16
// speedup vs baseline: 1.8163x; 1.8163x over previous
#include <cuda_runtime.h>
#include <math.h>

#define BB 16
#define NN 8
#define TT 65536
#define CHUNKS 32
#define TPB 256
#define TPC (TT / CHUNKS)        // 2048 floats per chunk per row
#define SUB 8                    // substeps per chunk
#define SCOLS 64                 // float4 columns per substep (256 floats)
#define NCPB 80                  // cells per batch: 64 cross + 8 nx + 8 ny
#define NCELL 64

// Scratch: [BB][80 cells][CHUNKS] -> cross-chunk sum contiguous (float4-able).
__device__ float g_part[BB * NCPB * CHUNKS];
__device__ unsigned int g_ctr;   // zero-init; last block resets to 0

__global__ __launch_bounds__(TPB, 4)
void sp_fused(const float* __restrict__ inp, const float* __restrict__ tgt,
              float* __restrict__ out, int out_size) {
    const int b = blockIdx.y;
    const int chunk = blockIdx.x;
    const int tid = threadIdx.x;
    const int col = tid & 63;      // float4 column within substep
    const int g = tid >> 6;        // i-group: X rows {2g,2g+1}; Y coop rows {g,g+4}
    const int warp = tid >> 5;
    const int lane = tid & 31;

    const float4* __restrict__ X = reinterpret_cast<const float4*>(inp)
                                   + (size_t)b * NN * (TT / 4) + (size_t)chunk * (TPC / 4);
    const float4* __restrict__ Y = reinterpret_cast<const float4*>(tgt)
                                   + (size_t)b * NN * (TT / 4) + (size_t)chunk * (TPC / 4);

    __shared__ float4 ybuf[2][NN][SCOLS];   // 16 KB double-buffered Y stage
    __shared__ float sred[TPB / 32][20];    // 16 cross + 2 nx + 2 ny per warp

    // ---- Phase 1: R9 schedule (dist-1 prefetch), dot-product compute ----
    float acc[2][NN];
#pragma unroll
    for (int i = 0; i < 2; i++)
#pragma unroll
        for (int j = 0; j < NN; j++) acc[i][j] = 0.f;
    float nx0 = 0.f, nx1 = 0.f;
    float ny0 = 0.f, ny1 = 0.f;

    // Cooperative Y mapping: thread loads rows g and g+4 at its col.
    float4 yreg0 = __ldg(&Y[(size_t)g * (TT / 4) + col]);
    float4 yreg1 = __ldg(&Y[(size_t)(g + 4) * (TT / 4) + col]);
    float4 xreg0 = __ldg(&X[(size_t)(2 * g) * (TT / 4) + col]);
    float4 xreg1 = __ldg(&X[(size_t)(2 * g + 1) * (TT / 4) + col]);
    // ny accumulation at load site (each Y element touched by exactly one thread).
    ny0 = fmaf(yreg0.x, yreg0.x, ny0); ny0 = fmaf(yreg0.y, yreg0.y, ny0);
    ny0 = fmaf(yreg0.z, yreg0.z, ny0); ny0 = fmaf(yreg0.w, yreg0.w, ny0);
    ny1 = fmaf(yreg1.x, yreg1.x, ny1); ny1 = fmaf(yreg1.y, yreg1.y, ny1);
    ny1 = fmaf(yreg1.z, yreg1.z, ny1); ny1 = fmaf(yreg1.w, yreg1.w, ny1);
    ybuf[0][g][col] = yreg0;
    ybuf[0][g + 4][col] = yreg1;
    __syncthreads();

#pragma unroll
    for (int s = 0; s < SUB; s++) {
        const int p = s & 1;
        const float4 xc0 = xreg0;
        const float4 xc1 = xreg1;
        if (s < SUB - 1) {
            const int t4 = (s + 1) * SCOLS + col;
            yreg0 = __ldg(&Y[(size_t)g * (TT / 4) + t4]);
            yreg1 = __ldg(&Y[(size_t)(g + 4) * (TT / 4) + t4]);
            xreg0 = __ldg(&X[(size_t)(2 * g) * (TT / 4) + t4]);
            xreg1 = __ldg(&X[(size_t)(2 * g + 1) * (TT / 4) + t4]);
        }
        // X norms for current substep.
        nx0 = fmaf(xc0.x, xc0.x, nx0); nx0 = fmaf(xc0.y, xc0.y, nx0);
        nx0 = fmaf(xc0.z, xc0.z, nx0); nx0 = fmaf(xc0.w, xc0.w, nx0);
        nx1 = fmaf(xc1.x, xc1.x, nx1); nx1 = fmaf(xc1.y, xc1.y, nx1);
        nx1 = fmaf(xc1.z, xc1.z, nx1); nx1 = fmaf(xc1.w, xc1.w, nx1);
#pragma unroll
        for (int j = 0; j < NN; j++) {
            const float4 y = ybuf[p][j][col];
            acc[0][j] = fmaf(xc0.x, y.x, acc[0][j]);
            acc[0][j] = fmaf(xc0.y, y.y, acc[0][j]);
            acc[0][j] = fmaf(xc0.z, y.z, acc[0][j]);
            acc[0][j] = fmaf(xc0.w, y.w, acc[0][j]);
            acc[1][j] = fmaf(xc1.x, y.x, acc[1][j]);
            acc[1][j] = fmaf(xc1.y, y.y, acc[1][j]);
            acc[1][j] = fmaf(xc1.z, y.z, acc[1][j]);
            acc[1][j] = fmaf(xc1.w, y.w, acc[1][j]);
        }
        if (s < SUB - 1) {
            ny0 = fmaf(yreg0.x, yreg0.x, ny0); ny0 = fmaf(yreg0.y, yreg0.y, ny0);
            ny0 = fmaf(yreg0.z, yreg0.z, ny0); ny0 = fmaf(yreg0.w, yreg0.w, ny0);
            ny1 = fmaf(yreg1.x, yreg1.x, ny1); ny1 = fmaf(yreg1.y, yreg1.y, ny1);
            ny1 = fmaf(yreg1.z, yreg1.z, ny1); ny1 = fmaf(yreg1.w, yreg1.w, ny1);
            ybuf[1 - p][g][col] = yreg0;
            ybuf[1 - p][g + 4][col] = yreg1;
            __syncthreads();
        }
    }

    // ---- Warp tree-reduce 20 values, stage per-warp, combine across warps ----
#pragma unroll
    for (int i = 0; i < 2; i++)
#pragma unroll
        for (int j = 0; j < NN; j++) {
            float v = acc[i][j];
            v += __shfl_xor_sync(0xffffffffu, v, 16);
            v += __shfl_xor_sync(0xffffffffu, v, 8);
            v += __shfl_xor_sync(0xffffffffu, v, 4);
            v += __shfl_xor_sync(0xffffffffu, v, 2);
            v += __shfl_xor_sync(0xffffffffu, v, 1);
            acc[i][j] = v;
        }
    {
        float v;
        v = nx0;
        v += __shfl_xor_sync(0xffffffffu, v, 16); v += __shfl_xor_sync(0xffffffffu, v, 8);
        v += __shfl_xor_sync(0xffffffffu, v, 4);  v += __shfl_xor_sync(0xffffffffu, v, 2);
        v += __shfl_xor_sync(0xffffffffu, v, 1);  nx0 = v;
        v = nx1;
        v += __shfl_xor_sync(0xffffffffu, v, 16); v += __shfl_xor_sync(0xffffffffu, v, 8);
        v += __shfl_xor_sync(0xffffffffu, v, 4);  v += __shfl_xor_sync(0xffffffffu, v, 2);
        v += __shfl_xor_sync(0xffffffffu, v, 1);  nx1 = v;
        v = ny0;
        v += __shfl_xor_sync(0xffffffffu, v, 16); v += __shfl_xor_sync(0xffffffffu, v, 8);
        v += __shfl_xor_sync(0xffffffffu, v, 4);  v += __shfl_xor_sync(0xffffffffu, v, 2);
        v += __shfl_xor_sync(0xffffffffu, v, 1);  ny0 = v;
        v = ny1;
        v += __shfl_xor_sync(0xffffffffu, v, 16); v += __shfl_xor_sync(0xffffffffu, v, 8);
        v += __shfl_xor_sync(0xffffffffu, v, 4);  v += __shfl_xor_sync(0xffffffffu, v, 2);
        v += __shfl_xor_sync(0xffffffffu, v, 1);  ny1 = v;
    }
    if (lane == 0) {
#pragma unroll
        for (int i = 0; i < 2; i++)
#pragma unroll
            for (int j = 0; j < NN; j++) sred[warp][i * NN + j] = acc[i][j];
        sred[warp][16] = nx0;
        sred[warp][17] = nx1;
        sred[warp][18] = ny0;
        sred[warp][19] = ny1;
    }
    __syncthreads();

    // i-group gi=i>>1 lives in warps {2gi, 2gi+1}; same for Y rows (g / g+4).
    float* const gp = &g_part[(size_t)b * NCPB * CHUNKS + chunk];
    if (tid < NCELL) {                        // cross cell (i,j)
        const int ci = tid >> 3, cj = tid & 7;
        const int gi = ci >> 1, ii = ci & 1;
        const float s = sred[2 * gi][ii * NN + cj] + sred[2 * gi + 1][ii * NN + cj];
        gp[(size_t)tid * CHUNKS] = s;
    } else if (tid < NCELL + 8) {             // nx row i (X row i = 2*gi+ii)
        const int i = tid - NCELL;
        const int gi = i >> 1, ii = i & 1;
        const float s = sred[2 * gi][16 + ii] + sred[2 * gi + 1][16 + ii];
        gp[(size_t)tid * CHUNKS] = s;
    } else if (tid < NCELL + 16) {            // ny row r (group r%4, slot 18/19)
        const int r = tid - NCELL - 8;
        const int gr = r & 3, hh = r >> 2;
        const float s = sred[2 * gr][18 + hh] + sred[2 * gr + 1][18 + hh];
        gp[(size_t)tid * CHUNKS] = s;
    }

    // ---- Arrival counter: last of 512 blocks finishes the job ----
    __threadfence();
    __syncthreads();
    __shared__ unsigned int s_last;
    if (tid == 0)
        s_last = (atomicAdd(&g_ctr, 1u) == (unsigned)(CHUNKS * BB - 1)) ? 1u : 0u;
    __syncthreads();
    if (!s_last) return;
    if (tid == 0) g_ctr = 0;       // reset for next graph replay

    // ---- Phase 2 (last block): chunk reduction, 32 contiguous floats/cell ----
    float* s_pl = reinterpret_cast<float*>(ybuf);   // reuse stage smem (5 KB)
    for (int cell = tid; cell < BB * NCPB; cell += TPB) {
        const float4* p = reinterpret_cast<const float4*>(&g_part[(size_t)cell * CHUNKS]);
        float s = 0.f;
#pragma unroll
        for (int q = 0; q < CHUNKS / 4; q++) {
            const float4 v = __ldcv(p + q);
            s += v.x + v.y + v.z + v.w;
        }
        s_pl[cell] = s;
    }
    __syncthreads();

    // ---- Phase 3: Sinkhorn (threads 0..127; thread = (batch sb, column sj)) ----
    float loss_t = 0.f;
    int aj[NN];
    const int sb = tid >> 3;
    const int sj = tid & 7;

    if (tid < 128) {
        const float* base = &s_pl[sb * NCPB];
        const float nyj = base[NCELL + 8 + sj];
        float pl[NN], z[NN];
#pragma unroll
        for (int i = 0; i < NN; i++) {
            // (x-y)^2 sum = nx_i + ny_j - 2*cross_ij, then mean over T
            pl[i] = (base[NCELL + i] + nyj - 2.f * base[i * NN + sj]) * (1.0f / (float)TT);
            z[i] = -pl[i];         // COLDNESS = 1
        }

#pragma unroll 1
        for (int it = 0; it < 10; it++) {
            float s = 0.f;
#pragma unroll
            for (int i = 0; i < NN; i++) s += __expf(z[i]);
            const float l = __logf(s);
#pragma unroll
            for (int i = 0; i < NN; i++) z[i] -= l;
            float e[NN];
#pragma unroll
            for (int i = 0; i < NN; i++) e[i] = __expf(z[i]);
#pragma unroll
            for (int off = 1; off < NN; off <<= 1)
#pragma unroll
                for (int i = 0; i < NN; i++)
                    e[i] += __shfl_xor_sync(0xffffffffu, e[i], off);
#pragma unroll
            for (int i = 0; i < NN; i++) z[i] -= __logf(e[i]);
        }

#pragma unroll
        for (int i = 0; i < NN; i++)
            loss_t += (pl[i] + z[i]) * __expf(z[i]);

        float av[NN];
#pragma unroll
        for (int i = 0; i < NN; i++) { av[i] = z[i]; aj[i] = sj; }
#pragma unroll
        for (int off = 1; off < NN; off <<= 1)
#pragma unroll
            for (int i = 0; i < NN; i++) {
                const float ov = __shfl_xor_sync(0xffffffffu, av[i], off);
                const int oj = __shfl_xor_sync(0xffffffffu, aj[i], off);
                if (ov > av[i] || (ov == av[i] && oj < aj[i])) { av[i] = ov; aj[i] = oj; }
            }
    }

    __shared__ float s_wloss[TPB / 32];
#pragma unroll
    for (int off = 16; off; off >>= 1)
        loss_t += __shfl_xor_sync(0xffffffffu, loss_t, off);
    if (lane == 0) s_wloss[warp] = loss_t;
    __syncthreads();
    float loss = 0.f;
    if (tid == 0) {
#pragma unroll
        for (int w = 0; w < 4; w++) loss += s_wloss[w];
        loss *= (1.0f / (float)BB);
    }

    // ---- Output: loss then pattern (fp32); defensive layouts ----
    const int full = 1 + BB * NN;   // 129
    if (out_size >= full) {
        if (tid == 0) out[0] = loss;
        if (tid < 128 && sj == 0) {
#pragma unroll
            for (int i = 0; i < NN; i++) out[1 + sb * NN + i] = (float)aj[i];
        }
        for (int idx = full + tid; idx < out_size; idx += TPB) out[idx] = 0.f;
    } else if (out_size == BB * NN) {
        if (tid < 128 && sj == 0) {
#pragma unroll
            for (int i = 0; i < NN; i++) out[sb * NN + i] = (float)aj[i];
        }
    } else {
        if (tid == 0 && out_size > 0) out[0] = loss;
        for (int idx = 1 + tid; idx < out_size; idx += TPB) out[idx] = 0.f;
    }
}

extern "C" void kernel_launch(void* const* d_in, const int* in_sizes, int n_in,
                              void* d_out, int out_size) {
    const float* inp = (const float*)d_in[0];
    const float* tgt = (const float*)d_in[1];

    dim3 grid(CHUNKS, BB);
    sp_fused<<<grid, TPB>>>(inp, tgt, (float*)d_out, out_size);
}